// round 15
// baseline (speedup 1.0000x reference)
#include <cuda_runtime.h>
#include <math.h>

// Problem constants
#define EE  4      // experts
#define BB  32     // batch
#define HH  7
#define LL  49     // H*W
#define DD  512    // dim
#define C2  1024   // 2*dim
#define RR  32     // DT_RANK
#define NS  16     // N_STATE
#define KDn 4      // directions
#define NSLOT (BB*2)   // 64 selected (b, expert) slots

// ---------------- scratch (device globals; no allocation allowed) ----------
__device__ float g_v [NSLOT*LL*DD];          // conv output v, slot-indexed (v-space)
__device__ float g_z [NSLOT*LL*DD];          // z half, slot-indexed
__device__ float g_ys[NSLOT*KDn*LL*DD];      // scan outputs (v-space)
__device__ float g_dt[NSLOT*KDn*LL*DD];      // softplus(dt) (v-space)
__device__ float g_Bm[NSLOT*KDn*LL*NS];      // B (v-space)
__device__ float g_Cm[NSLOT*KDn*LL*NS];      // C (v-space)
__device__ float g_xpwT[EE*DD*256];          // transposed x_proj_w: [e][d][k*64+c]
__device__ float g_dtwT[EE*KDn*RR*DD];       // transposed dt_proj_w: [e][k][r][d]
__device__ float g_poolp[4*NSLOT*DD];        // partial pooled sums per l-chunk
__device__ float g_raw[BB*EE];
__device__ float g_aux;
__device__ int   g_ctr;                      // last-block-done counter (self-reset)
__device__ int   g_topi[NSLOT];              // slot s -> expert  (b = s>>1)
__device__ float g_topv[NSLOT];              // slot s -> gate coeff

// ---------------- f32x2 packed FMA helpers (sm_103a) -----------------------
__device__ __forceinline__ unsigned long long pk2(float lo, float hi){
    unsigned long long r;
    asm("mov.b64 %0, {%1, %2};" : "=l"(r) : "f"(lo), "f"(hi));
    return r;
}
__device__ __forceinline__ void fma2(unsigned long long& d, unsigned long long a, unsigned long long b){
    asm("fma.rn.f32x2 %0, %1, %2, %0;" : "+l"(d) : "l"(a), "l"(b));
}
__device__ __forceinline__ void upk2(unsigned long long v, float& lo, float& hi){
    asm("mov.b64 {%0, %1}, %2;" : "=f"(lo), "=f"(hi) : "l"(v));
}
__device__ __forceinline__ float ex2f(float x){
    float r; asm("ex2.approx.f32 %0, %1;" : "=f"(r) : "f"(x)); return r;
}
__device__ __forceinline__ float lg2f(float x){
    float r; asm("lg2.approx.f32 %0, %1;" : "=f"(r) : "f"(x)); return r;
}

// ---------------- K0a: transpose x_proj_w -> g_xpwT [e][d][k*64+c] ---------
__global__ void k_wt(const float* __restrict__ xpw_){
    int row = blockIdx.x;            // ((e*4+k)*64 + c)
    int e  = row >> 8;
    int kc = row & 255;              // k*64+c
    const float* src = xpw_ + (size_t)row*DD;
    float* dst = g_xpwT + (size_t)e*DD*256 + kc;
    for (int d = threadIdx.x; d < DD; d += 128) dst[(size_t)d*256] = src[d];
}

// ---------------- K0b: transpose dt_proj_w -> g_dtwT [e][k][r][d] ----------
__global__ void k_wt2(const float* __restrict__ dtw_){
    int ek = blockIdx.x;             // e*4+k
    const float* src = dtw_ + (size_t)ek*DD*RR;
    float* dst = g_dtwT + (size_t)ek*DD*RR;
    for (int i = threadIdx.x; i < DD*RR; i += 512){
        int d = i >> 5, r = i & 31;
        dst[r*DD + d] = src[i];
    }
}

// ---------------- K1: gate softmax + fused top-k/aux (last block) ----------
__global__ void k_gate(const float* __restrict__ x, const float* __restrict__ wg,
                       const float* __restrict__ bg){
    int b = blockIdx.x, tid = threadIdx.x;           // 512 threads, tid = channel
    const float* xb = x + (size_t)b*LL*DD + tid;
    float s = 0.f;
    #pragma unroll 7
    for (int l = 0; l < LL; l++) s += xb[l*DD];
    s *= (1.f/49.f);
    float p0 = s*wg[tid*EE+0], p1 = s*wg[tid*EE+1];
    float p2 = s*wg[tid*EE+2], p3 = s*wg[tid*EE+3];
    #pragma unroll
    for (int o = 16; o; o >>= 1){
        p0 += __shfl_xor_sync(0xffffffffu, p0, o);
        p1 += __shfl_xor_sync(0xffffffffu, p1, o);
        p2 += __shfl_xor_sync(0xffffffffu, p2, o);
        p3 += __shfl_xor_sync(0xffffffffu, p3, o);
    }
    __shared__ float sp[16][4];
    int w = tid >> 5, lane = tid & 31;
    if (lane == 0){ sp[w][0]=p0; sp[w][1]=p1; sp[w][2]=p2; sp[w][3]=p3; }
    __syncthreads();
    if (tid == 0){
        float lg[4];
        for (int e = 0; e < 4; e++){
            float a = bg[e];
            for (int ww = 0; ww < 16; ww++) a += sp[ww][e];
            lg[e] = a;
        }
        float m = fmaxf(fmaxf(lg[0],lg[1]), fmaxf(lg[2],lg[3]));
        float ex[4], se = 0.f;
        for (int e = 0; e < 4; e++){ ex[e] = expf(lg[e]-m); se += ex[e]; }
        for (int e = 0; e < 4; e++) g_raw[b*4+e] = ex[e]/se;
    }
    __shared__ int sdone;
    if (tid == 0){
        __threadfence();
        int old = atomicAdd(&g_ctr, 1);
        sdone = (old == BB-1) ? 1 : 0;
    }
    __syncthreads();
    if (sdone){
        __threadfence();
        __shared__ float sraw[32][4];
        __shared__ float smask[32][4];
        __shared__ float sden[4];
        if (tid < 32){
            int bb = tid;
            float r[4];
            #pragma unroll
            for (int e = 0; e < 4; e++){ r[e] = g_raw[bb*4+e]; sraw[bb][e] = r[e]; }
            int i0 = 0; float m0 = r[0];
            #pragma unroll
            for (int e = 1; e < 4; e++) if (r[e] > m0){ m0 = r[e]; i0 = e; }
            int i1 = -1; float m1 = -1e30f;
            #pragma unroll
            for (int e = 0; e < 4; e++) if (e != i0 && r[e] > m1){ m1 = r[e]; i1 = e; }
            #pragma unroll
            for (int e = 0; e < 4; e++) smask[bb][e] = (e==i0 || e==i1) ? 1.f : 0.f;
        }
        __syncthreads();
        if (tid == 0){
            float aux = 0.f;
            for (int e = 0; e < 4; e++){
                float ds = 0.f, imp = 0.f, ld = 0.f;
                for (int bb = 0; bb < 32; bb++){
                    ds  += sraw[bb][e]*smask[bb][e];
                    imp += sraw[bb][e];
                    ld  += smask[bb][e];
                }
                sden[e] = ds + 1e-6f;
                imp *= (1.f/32.f); ld *= (1.f/32.f);
                aux += (ld-imp)*(ld-imp);
            }
            g_aux = 0.01f * aux * 0.25f;
        }
        __syncthreads();
        if (tid < 32){
            int bb = tid;
            float r[4];
            #pragma unroll
            for (int e = 0; e < 4; e++) r[e] = sraw[bb][e];
            int i0 = 0; float m0 = r[0];
            #pragma unroll
            for (int e = 1; e < 4; e++) if (r[e] > m0){ m0 = r[e]; i0 = e; }
            int i1 = -1; float m1 = -1e30f;
            #pragma unroll
            for (int e = 0; e < 4; e++) if (e != i0 && r[e] > m1){ m1 = r[e]; i1 = e; }
            const float cap = 40.f;   // int(1.25*32)
            float s0 = r[i0]*cap/sden[i0];
            float s1 = r[i1]*cap/sden[i1];
            int a0 = i0, a1 = i1; float v0 = s0, v1 = s1;
            if (v1 > v0 || (v1 == v0 && a1 < a0)){
                int t = a0; a0 = a1; a1 = t;
                float tv = v0; v0 = v1; v1 = tv;
            }
            g_topi[bb*2] = a0; g_topi[bb*2+1] = a1;
            g_topv[bb*2] = v0; g_topv[bb*2+1] = v1;
        }
        __syncthreads();
        if (tid == 0) g_ctr = 0;   // reset for next graph replay
    }
}

// ---------------- K3: in_proj GEMM + fused depthwise conv -> g_v -----------
// grid (64 slots, 2 roles) x 512 threads. sx TRANSPOSED in smem (stride 52).
// Thread: cth = tid&255 owns 2 cols; lg = tid>>8 owns l-pairs [lg*26, +26).
// Role 0 -> xin (smem) + conv -> g_v (v-space, 1x write); role 1 -> z.
#define SXS 52
#define IP_SMEM ((DD*SXS + LL*DD)*4)   // 106496 + 100352 = 206848
__global__ void __launch_bounds__(512, 1)
k_inproj(const float* __restrict__ x, const float* __restrict__ Wi,
         const float* __restrict__ bi, const float* __restrict__ cw,
         const float* __restrict__ cb){
    extern __shared__ float sm_[];
    float* sxT  = sm_;             // [DD][SXS]
    float* sxin = sm_ + DD*SXS;    // [LL][DD] (role 0 only)
    int s = blockIdx.x, role = blockIdx.y, tid = threadIdx.x;
    int b = s >> 1;
    int e = g_topi[s];
    const float* xb = x + (size_t)b*LL*DD;
    for (int i = tid; i < LL*DD; i += 512){
        int l = i >> 9, d = i & 511;
        sxT[d*SXS + l] = xb[i];
    }
    {
        int d = tid;
        sxT[d*SXS + 49] = 0.f; sxT[d*SXS + 50] = 0.f; sxT[d*SXS + 51] = 0.f;
    }
    __syncthreads();

    int cth = tid & 255, lg = tid >> 8;
    int c0 = cth*2;
    int lbase = lg*26;
    const float* We = Wi + (size_t)e*DD*C2 + role*DD + c0;
    float2 bia = *(const float2*)(bi + e*C2 + role*DD + c0);
    float* zout = g_z + (size_t)s*LL*DD;

    unsigned long long acc0[13], acc1[13];
    #pragma unroll
    for (int p = 0; p < 13; p++){ acc0[p] = 0ull; acc1[p] = 0ull; }

    #pragma unroll 8
    for (int kk = 0; kk < DD; kk++){
        float2 w = *(const float2*)(We + (size_t)kk*C2);
        unsigned long long w0 = pk2(w.x, w.x);
        unsigned long long w1 = pk2(w.y, w.y);
        const float* xr = sxT + kk*SXS + lbase;
        #pragma unroll
        for (int p = 0; p < 13; p++){
            unsigned long long xp = *(const unsigned long long*)(xr + 2*p);
            fma2(acc0[p], w0, xp);
            fma2(acc1[p], w1, xp);
        }
    }

    #pragma unroll
    for (int p = 0; p < 13; p++){
        int l0 = lbase + 2*p, l1 = l0 + 1;
        float a00, a01, a10, a11;
        upk2(acc0[p], a00, a01);
        upk2(acc1[p], a10, a11);
        if (l0 < LL){
            float2 o = make_float2(a00 + bia.x, a10 + bia.y);
            if (role == 0) *(float2*)(sxin + (size_t)l0*DD + c0) = o;
            else           *(float2*)(zout + (size_t)l0*DD + c0) = o;
        }
        if (l1 < LL){
            float2 o = make_float2(a01 + bia.x, a11 + bia.y);
            if (role == 0) *(float2*)(sxin + (size_t)l1*DD + c0) = o;
            else           *(float2*)(zout + (size_t)l1*DD + c0) = o;
        }
    }
    if (role != 0) return;
    __syncthreads();
    // ---- depthwise 3x3 conv + silu -> g_v (single write); d = tid ----
    float* vout = g_v + (size_t)s*LL*DD;
    {
        int d = tid;
        float w9[9];
        #pragma unroll
        for (int t = 0; t < 9; t++) w9[t] = cw[(e*DD+d)*9 + t];
        float bias = cb[e*DD+d];
        float row[3][7];
        #pragma unroll
        for (int j = 0; j < 7; j++){
            row[0][j] = sxin[(0*7+j)*DD + d];
            row[1][j] = sxin[(1*7+j)*DD + d];
        }
        #pragma unroll
        for (int i = 0; i < 7; i++){
            if (i < 6){
                #pragma unroll
                for (int j = 0; j < 7; j++)
                    row[(i+1)%3][j] = sxin[((i+1)*7+j)*DD + d];
            }
            const float* rm = (i > 0) ? row[(i-1)%3] : nullptr;
            const float* rc = row[i%3];
            const float* rp = (i < 6) ? row[(i+1)%3] : nullptr;
            #pragma unroll
            for (int j = 0; j < 7; j++){
                float a = bias;
                #pragma unroll
                for (int dj = 0; dj < 3; dj++){
                    int jj = j + dj - 1;
                    if (jj < 0 || jj > 6) continue;
                    if (i > 0) a += rm[jj]*w9[0*3+dj];
                    a += rc[jj]*w9[1*3+dj];
                    if (i < 6) a += rp[jj]*w9[2*3+dj];
                }
                float v = a / (1.f + __expf(-a));   // silu
                vout[(i*7+j)*DD + d] = v;
            }
        }
    }
}

// ---------------- K5a: merged x_dbl GEMM (all 4 dirs) + dt_proj ------------
// grid (64 slots, 2 roles) x 512 threads. Role r owns output rows
// kc = r*128..r*128+127 (directions k = 2r, 2r+1). v-space; permutation in
// k_scan. (Structure validated in R9 at rel_err 2.3e-7.)
#define SX2 52
#define XD_SMEM ((DD*SX2 + 128*SX2)*4)   // 106496 + 26624 = 133120
__global__ void __launch_bounds__(512, 1)
k_xdbl(const float* __restrict__ dtb_){
    extern __shared__ float sm[];
    float* vT = sm;                  // [DD][SX2]
    float* sY = sm + DD*SX2;         // [128][SX2]  Y rows for this role
    int s = blockIdx.x, role = blockIdx.y, tid = threadIdx.x;
    int e = g_topi[s];

    // load + transpose v
    const float* vsrc = g_v + (size_t)s*LL*DD;
    for (int i = tid; i < LL*DD; i += 512){
        int l = i >> 9, d = i & 511;
        vT[d*SX2 + l] = vsrc[i];
    }
    { int d = tid; vT[d*SX2+49]=0.f; vT[d*SX2+50]=0.f; vT[d*SX2+51]=0.f; }
    __syncthreads();

    // ---- phase A: Y[kc][l] = sum_d v[l][d] * xpwT[e][d][kc] ----
    int cth = tid & 63, lg = tid >> 6;           // 64 cth x 8 lg
    int kc0 = role*128 + cth*2;
    int lbase = (lg < 6) ? lg*6 : 36 + (lg-6)*8;
    int np    = (lg < 6) ? 3 : 4;
    unsigned long long a0[4], a1[4];
    #pragma unroll
    for (int p = 0; p < 4; p++){ a0[p] = 0ull; a1[p] = 0ull; }
    const float* Wp = g_xpwT + (size_t)e*DD*256 + kc0;
    #pragma unroll 4
    for (int kk = 0; kk < DD; kk++){
        float2 w = *(const float2*)(Wp + (size_t)kk*256);
        unsigned long long w0 = pk2(w.x, w.x);
        unsigned long long w1 = pk2(w.y, w.y);
        const float* xr = vT + kk*SX2 + lbase;
        #pragma unroll
        for (int p = 0; p < 4; p++){
            if (p < np){
                unsigned long long xp = *(const unsigned long long*)(xr + 2*p);
                fma2(a0[p], w0, xp);
                fma2(a1[p], w1, xp);
            }
        }
    }
    // stage to sY
    {
        int cl0 = cth*2;
        #pragma unroll
        for (int p = 0; p < 4; p++){
            if (p < np){
                float lo, hi;
                upk2(a0[p], lo, hi);
                sY[cl0*SX2 + lbase + 2*p] = lo;  sY[cl0*SX2 + lbase + 2*p + 1] = hi;
                upk2(a1[p], lo, hi);
                sY[(cl0+1)*SX2 + lbase + 2*p] = lo;  sY[(cl0+1)*SX2 + lbase + 2*p + 1] = hi;
            }
        }
    }
    __syncthreads();

    // ---- write B/C for this role's 2 directions ----
    for (int i = tid; i < 2*LL*NS; i += 512){
        int kloc = i / (LL*NS);
        int rem  = i - kloc*LL*NS;
        int l = rem >> 4, n = rem & 15;
        int k = role*2 + kloc;
        g_Bm[((size_t)(s*KDn + k)*LL + l)*NS + n] = sY[(kloc*64 + 32 + n)*SX2 + l];
        g_Cm[((size_t)(s*KDn + k)*LL + l)*NS + n] = sY[(kloc*64 + 48 + n)*SX2 + l];
    }

    // ---- dt_proj + softplus for the role's 2 directions; thread = dd ----
    int dd = tid;
    const float L2E = 1.44269504088896f;
    const float LN2 = 0.69314718055995f;
    #pragma unroll 1
    for (int kloc = 0; kloc < 2; kloc++){
        int k = role*2 + kloc;
        float bias = dtb_[(e*KDn + k)*DD + dd];
        // coalesced transposed dtw loads
        float wreg[32];
        {
            const float* wt = g_dtwT + (size_t)(e*KDn + k)*DD*RR + dd;
            #pragma unroll
            for (int r = 0; r < RR; r++) wreg[r] = wt[(size_t)r*DD];
        }
        unsigned long long acc[26];
        unsigned long long binit = pk2(bias, bias);
        #pragma unroll
        for (int t = 0; t < 26; t++) acc[t] = binit;
        const float* sb = sY + (kloc*64)*SX2;
        #pragma unroll 4
        for (int r = 0; r < RR; r++){
            unsigned long long wd = pk2(wreg[r], wreg[r]);
            const float* srow = sb + r*SX2;
            #pragma unroll
            for (int t = 0; t < 26; t++){
                unsigned long long xp = *(const unsigned long long*)(srow + 2*t);
                fma2(acc[t], wd, xp);
            }
        }
        float* dtout = g_dt + (size_t)(s*KDn + k)*LL*DD + dd;
        #pragma unroll
        for (int t = 0; t < 26; t++){
            float a_lo, a_hi;
            upk2(acc[t], a_lo, a_hi);
            int l0 = 2*t, l1 = 2*t + 1;
            if (l0 < LL){
                float dtv = fmaxf(a_lo, 0.f) + LN2*lg2f(1.f + ex2f(-fabsf(a_lo)*L2E));
                dtout[l0*DD] = dtv;
            }
            if (l1 < LL){
                float dtv = fmaxf(a_hi, 0.f) + LN2*lg2f(1.f + ex2f(-fabsf(a_hi)*L2E));
                dtout[l1*DD] = dtv;
            }
        }
    }
}

// ---------------- K5b: selective scan (v-space, permuted indexing) ---------
// grid = 256 blocks (s,k), 512 threads, thread = channel dd.
__global__ void __launch_bounds__(512, 2)
k_scan(const float* __restrict__ alog_, const float* __restrict__ ds_){
    __shared__ float sB[LL*NS];
    __shared__ float sC[LL*NS];
    __shared__ int   sPerm[LL];
    int idx = blockIdx.x;
    int k = idx & 3, s = idx >> 2;
    int e = g_topi[s];
    int dd = threadIdx.x;
    size_t skbase = (size_t)(s*KDn + k);
    {
        const float* Bg = g_Bm + skbase*LL*NS;
        const float* Cg = g_Cm + skbase*LL*NS;
        for (int i = dd; i < LL*NS; i += 512){ sB[i] = Bg[i]; sC[i] = Cg[i]; }
    }
    if (dd < LL){
        int t = dd;
        int tt = (k & 1) ? (48 - t) : t;
        int lsrc = (k >= 2) ? ((tt % 7)*7 + tt/7) : tt;
        sPerm[t] = lsrc;
    }
    float A[NS];
    {
        const float4* al = (const float4*)(alog_ + ((size_t)((e*KDn+k)*DD) + dd)*NS);
        const float L2E = 1.44269504088896f;
        #pragma unroll
        for (int q = 0; q < 4; q++){
            float4 v = al[q];
            A[q*4+0] = -__expf(v.x)*L2E; A[q*4+1] = -__expf(v.y)*L2E;
            A[q*4+2] = -__expf(v.z)*L2E; A[q*4+3] = -__expf(v.w)*L2E;
        }
    }
    float Dd = ds_[(e*KDn+k)*DD + dd];
    const float* dtp = g_dt + skbase*LL*DD + dd;
    const float* vp  = g_v  + (size_t)s*LL*DD + dd;
    float*       ysp = g_ys + skbase*LL*DD + dd;
    __syncthreads();
    float h[NS];
    #pragma unroll
    for (int n = 0; n < NS; n++) h[n] = 0.f;
    int lcur = sPerm[0];
    float dtc = dtp[lcur*DD], xvc = vp[lcur*DD];
    #pragma unroll 1
    for (int t = 0; t < LL; t++){
        int lnext = (t < LL-1) ? sPerm[t+1] : 0;
        float dtn = 0.f, xvn = 0.f;
        if (t < LL-1){ dtn = dtp[lnext*DD]; xvn = vp[lnext*DD]; }
        float dx = dtc*xvc;
        const float* Bl = sB + lcur*NS;
        const float* Cl = sC + lcur*NS;
        float y = 0.f;
        #pragma unroll
        for (int n = 0; n < NS; n++){
            h[n] = h[n]*ex2f(dtc*A[n]) + dx*Bl[n];
            y += h[n]*Cl[n];
        }
        ysp[lcur*DD] = y + Dd*xvc;
        lcur = lnext; dtc = dtn; xvc = xvn;
    }
}

// ---------------- block reduction (sum, sumsq) over 512 threads ------------
__device__ __forceinline__ float2 blockReduce2(float a, float b){
    __shared__ float sa[16], sb[16];
    __shared__ float2 res;
    int lane = threadIdx.x & 31, w = threadIdx.x >> 5;
    #pragma unroll
    for (int o = 16; o; o >>= 1){
        a += __shfl_xor_sync(0xffffffffu, a, o);
        b += __shfl_xor_sync(0xffffffffu, b, o);
    }
    __syncthreads();
    if (lane == 0){ sa[w] = a; sb[w] = b; }
    __syncthreads();
    if (w == 0){
        a = (lane < 16) ? sa[lane] : 0.f;
        b = (lane < 16) ? sb[lane] : 0.f;
        #pragma unroll
        for (int o = 8; o; o >>= 1){
            a += __shfl_xor_sync(0xffffffffu, a, o);
            b += __shfl_xor_sync(0xffffffffu, b, o);
        }
        if (lane == 0){ res.x = a; res.y = b; }
    }
    __syncthreads();
    return res;
}

// ---------------- K7: combine dirs + LN + silu(z) gate, CHUNKED over l -----
// grid (64 slots, 4 chunks) x 512 threads. v-space: ys sums uniformly over k.
#define CHL 13
__global__ void __launch_bounds__(512)
k_combine(const float* __restrict__ og_, const float* __restrict__ ob_){
    __shared__ float sv[CHL*DD];
    __shared__ float smu[16], srs[16];
    int s = blockIdx.x, chunk = blockIdx.y, d = threadIdx.x;
    int e = g_topi[s];
    int l0 = chunk*CHL;
    int nl = (chunk < 3) ? CHL : (LL - 3*CHL);   // 13,13,13,10
    const float* y0 = g_ys + (size_t)(s*KDn + 0)*LL*DD;
    const float* y1 = g_ys + (size_t)(s*KDn + 1)*LL*DD;
    const float* y2 = g_ys + (size_t)(s*KDn + 2)*LL*DD;
    const float* y3 = g_ys + (size_t)(s*KDn + 3)*LL*DD;
    for (int t = 0; t < nl; t++){
        int o = (l0 + t)*DD + d;
        sv[t*DD + d] = y0[o] + y1[o] + y2[o] + y3[o];
    }
    __syncthreads();
    int w = d >> 5, lane = d & 31;
    if (w < nl){
        int t = w;
        float a = 0.f, s2 = 0.f;
        #pragma unroll
        for (int jj = 0; jj < 16; jj++){
            float xv = sv[t*DD + lane + 32*jj];
            a += xv; s2 += xv*xv;
        }
        #pragma unroll
        for (int o = 16; o; o >>= 1){
            a  += __shfl_xor_sync(0xffffffffu, a, o);
            s2 += __shfl_xor_sync(0xffffffffu, s2, o);
        }
        if (lane == 0){
            float mu = a*(1.f/512.f);
            float var = s2*(1.f/512.f) - mu*mu;
            smu[t] = mu;
            srs[t] = rsqrtf(var + 1e-5f);
        }
    }
    __syncthreads();
    float og = og_[e*DD+d], ob = ob_[e*DD+d];
    const float* zrow = g_z + (size_t)s*LL*DD + d;
    float pooled = 0.f;
    for (int t = 0; t < nl; t++){
        int l = l0 + t;
        float v = sv[t*DD + d];
        float yn = (v - smu[t])*srs[t]*og + ob;
        float z = zrow[l*DD];
        pooled += yn * (z / (1.f + __expf(-z)));
    }
    g_poolp[(chunk*NSLOT + s)*DD + d] = pooled;
}

// ---------------- K8: final pooled LN per slot + top-2 mix + aux -----------
__global__ void __launch_bounds__(512)
k_mix(float* __restrict__ out, int out_size,
      const float* __restrict__ ng_, const float* __restrict__ nb_){
    int b = blockIdx.x, d = threadIdx.x;
    float res = 0.f;
    #pragma unroll 1
    for (int j = 0; j < 2; j++){
        int s = b*2 + j;
        int e = g_topi[s];
        float pooled = (g_poolp[(0*NSLOT + s)*DD + d]
                      + g_poolp[(1*NSLOT + s)*DD + d]
                      + g_poolp[(2*NSLOT + s)*DD + d]
                      + g_poolp[(3*NSLOT + s)*DD + d]) * (1.f/49.f);
        float2 ss = blockReduce2(pooled, pooled*pooled);
        float mu = ss.x*(1.f/512.f);
        float var = ss.y*(1.f/512.f) - mu*mu;
        float rs = rsqrtf(var + 1e-5f);
        float yn = (pooled - mu)*rs*ng_[e*DD+d] + nb_[e*DD+d];
        res += g_topv[s] * yn;
    }
    out[b*DD + d] = res;
    if (b == 0 && d == 0 && out_size > BB*DD) out[BB*DD] = g_aux;
}

// ---------------- launch ----------------------------------------------------
extern "C" void kernel_launch(void* const* d_in, const int* in_sizes, int n_in,
                              void* d_out, int out_size){
    const float* x    = (const float*)d_in[0];
    const float* wg   = (const float*)d_in[1];
    const float* bg   = (const float*)d_in[2];
    const float* ipw  = (const float*)d_in[3];
    const float* ipb  = (const float*)d_in[4];
    const float* cw   = (const float*)d_in[5];
    const float* cb   = (const float*)d_in[6];
    const float* xpw  = (const float*)d_in[7];
    const float* dtw  = (const float*)d_in[8];
    const float* dtb  = (const float*)d_in[9];
    const float* alog = (const float*)d_in[10];
    const float* ds   = (const float*)d_in[11];
    const float* ong  = (const float*)d_in[12];
    const float* onb  = (const float*)d_in[13];
    const float* ng   = (const float*)d_in[14];
    const float* nb   = (const float*)d_in[15];
    float* out = (float*)d_out;

    cudaFuncSetAttribute(k_inproj, cudaFuncAttributeMaxDynamicSharedMemorySize, IP_SMEM);
    cudaFuncSetAttribute(k_xdbl,   cudaFuncAttributeMaxDynamicSharedMemorySize, XD_SMEM);

    k_wt      <<<EE*KDn*64, 128>>>(xpw);
    k_wt2     <<<EE*KDn, 512>>>(dtw);
    k_gate    <<<BB, 512>>>(x, wg, bg);
    k_inproj  <<<dim3(NSLOT, 2), 512, IP_SMEM>>>(x, ipw, ipb, cw, cb);
    k_xdbl    <<<dim3(NSLOT, 2), 512, XD_SMEM>>>(dtb);
    k_scan    <<<NSLOT*KDn, 512>>>(alog, ds);
    k_combine <<<dim3(NSLOT, 4), 512>>>(ong, onb);
    k_mix     <<<BB, 512>>>(out, out_size, ng, nb);
}

// round 16
// speedup vs baseline: 1.0470x; 1.0470x over previous
#include <cuda_runtime.h>
#include <math.h>

// Problem constants
#define EE  4      // experts
#define BB  32     // batch
#define HH  7
#define LL  49     // H*W
#define DD  512    // dim
#define C2  1024   // 2*dim
#define RR  32     // DT_RANK
#define NS  16     // N_STATE
#define KDn 4      // directions
#define NSLOT (BB*2)   // 64 selected (b, expert) slots

// ---------------- scratch (device globals; no allocation allowed) ----------
__device__ float g_v [NSLOT*LL*DD];          // conv output v, slot-indexed (v-space)
__device__ float g_z [NSLOT*LL*DD];          // z half, slot-indexed
__device__ float g_ys[NSLOT*KDn*LL*DD];      // scan outputs (v-space)
__device__ float g_dt[NSLOT*KDn*LL*DD];      // softplus(dt) (v-space)
__device__ float g_Bm[NSLOT*KDn*LL*NS];      // B (v-space)
__device__ float g_Cm[NSLOT*KDn*LL*NS];      // C (v-space)
__device__ float g_xpwT[EE*DD*256];          // transposed x_proj_w: [e][d][k*64+c]
__device__ float g_dtwT[EE*KDn*RR*DD];       // transposed dt_proj_w: [e][k][r][d]
__device__ float g_poolp[4*NSLOT*DD];        // partial pooled sums per l-chunk
__device__ float g_raw[BB*EE];
__device__ float g_aux;
__device__ int   g_ctr;                      // last-block-done counter (self-reset)
__device__ int   g_topi[NSLOT];              // slot s -> expert  (b = s>>1)
__device__ float g_topv[NSLOT];              // slot s -> gate coeff

// ---------------- f32x2 packed FMA helpers (sm_103a) -----------------------
__device__ __forceinline__ unsigned long long pk2(float lo, float hi){
    unsigned long long r;
    asm("mov.b64 %0, {%1, %2};" : "=l"(r) : "f"(lo), "f"(hi));
    return r;
}
__device__ __forceinline__ void fma2(unsigned long long& d, unsigned long long a, unsigned long long b){
    asm("fma.rn.f32x2 %0, %1, %2, %0;" : "+l"(d) : "l"(a), "l"(b));
}
__device__ __forceinline__ void upk2(unsigned long long v, float& lo, float& hi){
    asm("mov.b64 {%0, %1}, %2;" : "=f"(lo), "=f"(hi) : "l"(v));
}
__device__ __forceinline__ float ex2f(float x){
    float r; asm("ex2.approx.f32 %0, %1;" : "=f"(r) : "f"(x)); return r;
}
__device__ __forceinline__ float lg2f(float x){
    float r; asm("lg2.approx.f32 %0, %1;" : "=f"(r) : "f"(x)); return r;
}

// ---------------- K0a: coalesced tiled transpose xpw -> g_xpwT -------------
// src: [(e*256 + kc)][512 d]  ->  dst: [e][d][kc]
// grid (EE, 8 kc-tiles, 16 d-tiles), block (32,8)
__global__ void k_wt(const float* __restrict__ xpw_){
    __shared__ float tile[32][33];
    int e = blockIdx.x, kt = blockIdx.y, dt = blockIdx.z;
    int tx = threadIdx.x, ty = threadIdx.y;
    #pragma unroll
    for (int i = 0; i < 4; i++){
        int kc = kt*32 + ty + 8*i;
        tile[ty + 8*i][tx] = xpw_[((size_t)e*256 + kc)*DD + dt*32 + tx];
    }
    __syncthreads();
    #pragma unroll
    for (int i = 0; i < 4; i++){
        int d = dt*32 + ty + 8*i;
        g_xpwT[(size_t)e*DD*256 + (size_t)d*256 + kt*32 + tx] = tile[tx][ty + 8*i];
    }
}

// ---------------- K0b: coalesced tiled transpose dtw -> g_dtwT -------------
// src per ek: [512 d][32 r] -> dst: [32 r][512 d]
// grid (16 ek, 16 d-tiles), block (32,8)
__global__ void k_wt2(const float* __restrict__ dtw_){
    __shared__ float tile[32][33];
    int ek = blockIdx.x, dt = blockIdx.y;
    int tx = threadIdx.x, ty = threadIdx.y;
    const float* src = dtw_ + (size_t)ek*DD*RR;
    float* dst = g_dtwT + (size_t)ek*DD*RR;
    #pragma unroll
    for (int i = 0; i < 4; i++){
        int d = dt*32 + ty + 8*i;
        tile[ty + 8*i][tx] = src[(size_t)d*RR + tx];   // tile[di][ri]
    }
    __syncthreads();
    #pragma unroll
    for (int i = 0; i < 4; i++){
        int r = ty + 8*i;
        dst[(size_t)r*DD + dt*32 + tx] = tile[tx][r];
    }
}

// ---------------- K1: gate softmax + fused top-k/aux (last block) ----------
__global__ void k_gate(const float* __restrict__ x, const float* __restrict__ wg,
                       const float* __restrict__ bg){
    int b = blockIdx.x, tid = threadIdx.x;           // 512 threads, tid = channel
    const float* xb = x + (size_t)b*LL*DD + tid;
    float s = 0.f;
    #pragma unroll 7
    for (int l = 0; l < LL; l++) s += xb[l*DD];
    s *= (1.f/49.f);
    float p0 = s*wg[tid*EE+0], p1 = s*wg[tid*EE+1];
    float p2 = s*wg[tid*EE+2], p3 = s*wg[tid*EE+3];
    #pragma unroll
    for (int o = 16; o; o >>= 1){
        p0 += __shfl_xor_sync(0xffffffffu, p0, o);
        p1 += __shfl_xor_sync(0xffffffffu, p1, o);
        p2 += __shfl_xor_sync(0xffffffffu, p2, o);
        p3 += __shfl_xor_sync(0xffffffffu, p3, o);
    }
    __shared__ float sp[16][4];
    int w = tid >> 5, lane = tid & 31;
    if (lane == 0){ sp[w][0]=p0; sp[w][1]=p1; sp[w][2]=p2; sp[w][3]=p3; }
    __syncthreads();
    if (tid == 0){
        float lg[4];
        for (int e = 0; e < 4; e++){
            float a = bg[e];
            for (int ww = 0; ww < 16; ww++) a += sp[ww][e];
            lg[e] = a;
        }
        float m = fmaxf(fmaxf(lg[0],lg[1]), fmaxf(lg[2],lg[3]));
        float ex[4], se = 0.f;
        for (int e = 0; e < 4; e++){ ex[e] = expf(lg[e]-m); se += ex[e]; }
        for (int e = 0; e < 4; e++) g_raw[b*4+e] = ex[e]/se;
    }
    __shared__ int sdone;
    if (tid == 0){
        __threadfence();
        int old = atomicAdd(&g_ctr, 1);
        sdone = (old == BB-1) ? 1 : 0;
    }
    __syncthreads();
    if (sdone){
        __threadfence();
        __shared__ float sraw[32][4];
        __shared__ float smask[32][4];
        __shared__ float sden[4];
        if (tid < 32){
            int bb = tid;
            float r[4];
            #pragma unroll
            for (int e = 0; e < 4; e++){ r[e] = g_raw[bb*4+e]; sraw[bb][e] = r[e]; }
            int i0 = 0; float m0 = r[0];
            #pragma unroll
            for (int e = 1; e < 4; e++) if (r[e] > m0){ m0 = r[e]; i0 = e; }
            int i1 = -1; float m1 = -1e30f;
            #pragma unroll
            for (int e = 0; e < 4; e++) if (e != i0 && r[e] > m1){ m1 = r[e]; i1 = e; }
            #pragma unroll
            for (int e = 0; e < 4; e++) smask[bb][e] = (e==i0 || e==i1) ? 1.f : 0.f;
        }
        __syncthreads();
        if (tid == 0){
            float aux = 0.f;
            for (int e = 0; e < 4; e++){
                float ds = 0.f, imp = 0.f, ld = 0.f;
                for (int bb = 0; bb < 32; bb++){
                    ds  += sraw[bb][e]*smask[bb][e];
                    imp += sraw[bb][e];
                    ld  += smask[bb][e];
                }
                sden[e] = ds + 1e-6f;
                imp *= (1.f/32.f); ld *= (1.f/32.f);
                aux += (ld-imp)*(ld-imp);
            }
            g_aux = 0.01f * aux * 0.25f;
        }
        __syncthreads();
        if (tid < 32){
            int bb = tid;
            float r[4];
            #pragma unroll
            for (int e = 0; e < 4; e++) r[e] = sraw[bb][e];
            int i0 = 0; float m0 = r[0];
            #pragma unroll
            for (int e = 1; e < 4; e++) if (r[e] > m0){ m0 = r[e]; i0 = e; }
            int i1 = -1; float m1 = -1e30f;
            #pragma unroll
            for (int e = 0; e < 4; e++) if (e != i0 && r[e] > m1){ m1 = r[e]; i1 = e; }
            const float cap = 40.f;   // int(1.25*32)
            float s0 = r[i0]*cap/sden[i0];
            float s1 = r[i1]*cap/sden[i1];
            int a0 = i0, a1 = i1; float v0 = s0, v1 = s1;
            if (v1 > v0 || (v1 == v0 && a1 < a0)){
                int t = a0; a0 = a1; a1 = t;
                float tv = v0; v0 = v1; v1 = tv;
            }
            g_topi[bb*2] = a0; g_topi[bb*2+1] = a1;
            g_topv[bb*2] = v0; g_topv[bb*2+1] = v1;
        }
        __syncthreads();
        if (tid == 0) g_ctr = 0;   // reset for next graph replay
    }
}

// ---------------- K3: in_proj GEMM + fused depthwise conv -> g_v -----------
// grid (64 slots, 2 roles) x 512 threads. sx TRANSPOSED in smem (stride 52).
// Thread: cth = tid&255 owns 2 cols; lg = tid>>8 owns 14 l-pairs:
//   lg0: l 0..27, lg1: l 24..51 (l 24..27 overlap computed twice — benign
//   same-value double store; rows 49..51 are zero pad). x operand loaded as
//   LDS.128 (ulonglong2 = 2 f32x2 pairs), 7 per kk instead of 13 LDS.64.
#define SXS 52
#define IP_SMEM ((DD*SXS + LL*DD)*4)   // 106496 + 100352 = 206848
__global__ void __launch_bounds__(512, 1)
k_inproj(const float* __restrict__ x, const float* __restrict__ Wi,
         const float* __restrict__ bi, const float* __restrict__ cw,
         const float* __restrict__ cb){
    extern __shared__ float sm_[];
    float* sxT  = sm_;             // [DD][SXS]
    float* sxin = sm_ + DD*SXS;    // [LL][DD] (role 0 only)
    int s = blockIdx.x, role = blockIdx.y, tid = threadIdx.x;
    int b = s >> 1;
    int e = g_topi[s];
    const float* xb = x + (size_t)b*LL*DD;
    for (int i = tid; i < LL*DD; i += 512){
        int l = i >> 9, d = i & 511;
        sxT[d*SXS + l] = xb[i];
    }
    {
        int d = tid;
        sxT[d*SXS + 49] = 0.f; sxT[d*SXS + 50] = 0.f; sxT[d*SXS + 51] = 0.f;
    }
    __syncthreads();

    int cth = tid & 255, lg = tid >> 8;
    int c0 = cth*2;
    int lbase = lg*24;                 // 0 or 24; both 16B-aligned in sxT rows
    const float* We = Wi + (size_t)e*DD*C2 + role*DD + c0;
    float2 bia = *(const float2*)(bi + e*C2 + role*DD + c0);
    float* zout = g_z + (size_t)s*LL*DD;

    unsigned long long acc0[14], acc1[14];
    #pragma unroll
    for (int p = 0; p < 14; p++){ acc0[p] = 0ull; acc1[p] = 0ull; }

    #pragma unroll 8
    for (int kk = 0; kk < DD; kk++){
        float2 w = *(const float2*)(We + (size_t)kk*C2);
        unsigned long long w0 = pk2(w.x, w.x);
        unsigned long long w1 = pk2(w.y, w.y);
        const ulonglong2* xr = (const ulonglong2*)(sxT + kk*SXS + lbase);
        #pragma unroll
        for (int q = 0; q < 7; q++){
            ulonglong2 xq = xr[q];          // LDS.128: pairs (2q, 2q+1)
            fma2(acc0[2*q],   w0, xq.x);
            fma2(acc1[2*q],   w1, xq.x);
            fma2(acc0[2*q+1], w0, xq.y);
            fma2(acc1[2*q+1], w1, xq.y);
        }
    }

    #pragma unroll
    for (int p = 0; p < 14; p++){
        int l0 = lbase + 2*p, l1 = l0 + 1;
        float a00, a01, a10, a11;
        upk2(acc0[p], a00, a01);
        upk2(acc1[p], a10, a11);
        if (l0 < LL){
            float2 o = make_float2(a00 + bia.x, a10 + bia.y);
            if (role == 0) *(float2*)(sxin + (size_t)l0*DD + c0) = o;
            else           *(float2*)(zout + (size_t)l0*DD + c0) = o;
        }
        if (l1 < LL){
            float2 o = make_float2(a01 + bia.x, a11 + bia.y);
            if (role == 0) *(float2*)(sxin + (size_t)l1*DD + c0) = o;
            else           *(float2*)(zout + (size_t)l1*DD + c0) = o;
        }
    }
    if (role != 0) return;
    __syncthreads();
    // ---- depthwise 3x3 conv + silu -> g_v (single write); d = tid ----
    float* vout = g_v + (size_t)s*LL*DD;
    {
        int d = tid;
        float w9[9];
        #pragma unroll
        for (int t = 0; t < 9; t++) w9[t] = cw[(e*DD+d)*9 + t];
        float bias = cb[e*DD+d];
        float row[3][7];
        #pragma unroll
        for (int j = 0; j < 7; j++){
            row[0][j] = sxin[(0*7+j)*DD + d];
            row[1][j] = sxin[(1*7+j)*DD + d];
        }
        #pragma unroll
        for (int i = 0; i < 7; i++){
            if (i < 6){
                #pragma unroll
                for (int j = 0; j < 7; j++)
                    row[(i+1)%3][j] = sxin[((i+1)*7+j)*DD + d];
            }
            const float* rm = (i > 0) ? row[(i-1)%3] : nullptr;
            const float* rc = row[i%3];
            const float* rp = (i < 6) ? row[(i+1)%3] : nullptr;
            #pragma unroll
            for (int j = 0; j < 7; j++){
                float a = bias;
                #pragma unroll
                for (int dj = 0; dj < 3; dj++){
                    int jj = j + dj - 1;
                    if (jj < 0 || jj > 6) continue;
                    if (i > 0) a += rm[jj]*w9[0*3+dj];
                    a += rc[jj]*w9[1*3+dj];
                    if (i < 6) a += rp[jj]*w9[2*3+dj];
                }
                float v = a / (1.f + __expf(-a));   // silu
                vout[(i*7+j)*DD + d] = v;
            }
        }
    }
}

// ---------------- K5a: merged x_dbl GEMM (all 4 dirs) + dt_proj ------------
// grid (64 slots, 2 roles) x 512 threads. Role r owns output rows
// kc = r*128..r*128+127 (directions k = 2r, 2r+1). v-space; permutation in
// k_scan.
#define SX2 52
#define XD_SMEM ((DD*SX2 + 128*SX2)*4)   // 106496 + 26624 = 133120
__global__ void __launch_bounds__(512, 1)
k_xdbl(const float* __restrict__ dtb_){
    extern __shared__ float sm[];
    float* vT = sm;                  // [DD][SX2]
    float* sY = sm + DD*SX2;         // [128][SX2]  Y rows for this role
    int s = blockIdx.x, role = blockIdx.y, tid = threadIdx.x;
    int e = g_topi[s];

    // load + transpose v
    const float* vsrc = g_v + (size_t)s*LL*DD;
    for (int i = tid; i < LL*DD; i += 512){
        int l = i >> 9, d = i & 511;
        vT[d*SX2 + l] = vsrc[i];
    }
    { int d = tid; vT[d*SX2+49]=0.f; vT[d*SX2+50]=0.f; vT[d*SX2+51]=0.f; }
    __syncthreads();

    // ---- phase A: Y[kc][l] = sum_d v[l][d] * xpwT[e][d][kc] ----
    int cth = tid & 63, lg = tid >> 6;           // 64 cth x 8 lg
    int kc0 = role*128 + cth*2;
    int lbase = (lg < 6) ? lg*6 : 36 + (lg-6)*8;
    int np    = (lg < 6) ? 3 : 4;
    unsigned long long a0[4], a1[4];
    #pragma unroll
    for (int p = 0; p < 4; p++){ a0[p] = 0ull; a1[p] = 0ull; }
    const float* Wp = g_xpwT + (size_t)e*DD*256 + kc0;
    #pragma unroll 4
    for (int kk = 0; kk < DD; kk++){
        float2 w = *(const float2*)(Wp + (size_t)kk*256);
        unsigned long long w0 = pk2(w.x, w.x);
        unsigned long long w1 = pk2(w.y, w.y);
        const float* xr = vT + kk*SX2 + lbase;
        #pragma unroll
        for (int p = 0; p < 4; p++){
            if (p < np){
                unsigned long long xp = *(const unsigned long long*)(xr + 2*p);
                fma2(a0[p], w0, xp);
                fma2(a1[p], w1, xp);
            }
        }
    }
    // stage to sY
    {
        int cl0 = cth*2;
        #pragma unroll
        for (int p = 0; p < 4; p++){
            if (p < np){
                float lo, hi;
                upk2(a0[p], lo, hi);
                sY[cl0*SX2 + lbase + 2*p] = lo;  sY[cl0*SX2 + lbase + 2*p + 1] = hi;
                upk2(a1[p], lo, hi);
                sY[(cl0+1)*SX2 + lbase + 2*p] = lo;  sY[(cl0+1)*SX2 + lbase + 2*p + 1] = hi;
            }
        }
    }
    __syncthreads();

    // ---- write B/C for this role's 2 directions ----
    for (int i = tid; i < 2*LL*NS; i += 512){
        int kloc = i / (LL*NS);
        int rem  = i - kloc*LL*NS;
        int l = rem >> 4, n = rem & 15;
        int k = role*2 + kloc;
        g_Bm[((size_t)(s*KDn + k)*LL + l)*NS + n] = sY[(kloc*64 + 32 + n)*SX2 + l];
        g_Cm[((size_t)(s*KDn + k)*LL + l)*NS + n] = sY[(kloc*64 + 48 + n)*SX2 + l];
    }

    // ---- dt_proj + softplus for the role's 2 directions; thread = dd ----
    int dd = tid;
    const float L2E = 1.44269504088896f;
    const float LN2 = 0.69314718055995f;
    #pragma unroll 1
    for (int kloc = 0; kloc < 2; kloc++){
        int k = role*2 + kloc;
        float bias = dtb_[(e*KDn + k)*DD + dd];
        float wreg[32];
        {
            const float* wt = g_dtwT + (size_t)(e*KDn + k)*DD*RR + dd;
            #pragma unroll
            for (int r = 0; r < RR; r++) wreg[r] = wt[(size_t)r*DD];
        }
        unsigned long long acc[26];
        unsigned long long binit = pk2(bias, bias);
        #pragma unroll
        for (int t = 0; t < 26; t++) acc[t] = binit;
        const float* sb = sY + (kloc*64)*SX2;
        #pragma unroll 4
        for (int r = 0; r < RR; r++){
            unsigned long long wd = pk2(wreg[r], wreg[r]);
            const float* srow = sb + r*SX2;
            #pragma unroll
            for (int t = 0; t < 26; t++){
                unsigned long long xp = *(const unsigned long long*)(srow + 2*t);
                fma2(acc[t], wd, xp);
            }
        }
        float* dtout = g_dt + (size_t)(s*KDn + k)*LL*DD + dd;
        #pragma unroll
        for (int t = 0; t < 26; t++){
            float a_lo, a_hi;
            upk2(acc[t], a_lo, a_hi);
            int l0 = 2*t, l1 = 2*t + 1;
            if (l0 < LL){
                float dtv = fmaxf(a_lo, 0.f) + LN2*lg2f(1.f + ex2f(-fabsf(a_lo)*L2E));
                dtout[l0*DD] = dtv;
            }
            if (l1 < LL){
                float dtv = fmaxf(a_hi, 0.f) + LN2*lg2f(1.f + ex2f(-fabsf(a_hi)*L2E));
                dtout[l1*DD] = dtv;
            }
        }
    }
}

// ---------------- K5b: selective scan (v-space, ALU permutation) -----------
// grid = 256 blocks (s,k), 512 threads, thread = channel dd.
__device__ __forceinline__ int permf(int k, int t){
    int tt = (k & 1) ? (48 - t) : t;
    if (k >= 2){
        int q = tt / 7;
        return (tt - 7*q)*7 + q;
    }
    return tt;
}
__global__ void __launch_bounds__(512, 2)
k_scan(const float* __restrict__ alog_, const float* __restrict__ ds_){
    __shared__ float sB[LL*NS];
    __shared__ float sC[LL*NS];
    int idx = blockIdx.x;
    int k = idx & 3, s = idx >> 2;
    int e = g_topi[s];
    int dd = threadIdx.x;
    size_t skbase = (size_t)(s*KDn + k);
    {
        const float* Bg = g_Bm + skbase*LL*NS;
        const float* Cg = g_Cm + skbase*LL*NS;
        for (int i = dd; i < LL*NS; i += 512){ sB[i] = Bg[i]; sC[i] = Cg[i]; }
    }
    float A[NS];
    {
        const float4* al = (const float4*)(alog_ + ((size_t)((e*KDn+k)*DD) + dd)*NS);
        const float L2E = 1.44269504088896f;
        #pragma unroll
        for (int q = 0; q < 4; q++){
            float4 v = al[q];
            A[q*4+0] = -__expf(v.x)*L2E; A[q*4+1] = -__expf(v.y)*L2E;
            A[q*4+2] = -__expf(v.z)*L2E; A[q*4+3] = -__expf(v.w)*L2E;
        }
    }
    float Dd = ds_[(e*KDn+k)*DD + dd];
    const float* dtp = g_dt + skbase*LL*DD + dd;
    const float* vp  = g_v  + (size_t)s*LL*DD + dd;
    float*       ysp = g_ys + skbase*LL*DD + dd;
    __syncthreads();
    float h[NS];
    #pragma unroll
    for (int n = 0; n < NS; n++) h[n] = 0.f;
    int lcur = permf(k, 0);
    float dtc = dtp[lcur*DD], xvc = vp[lcur*DD];
    #pragma unroll 1
    for (int t = 0; t < LL; t++){
        int lnext = (t < LL-1) ? permf(k, t+1) : 0;
        float dtn = 0.f, xvn = 0.f;
        if (t < LL-1){ dtn = dtp[lnext*DD]; xvn = vp[lnext*DD]; }
        float dx = dtc*xvc;
        const float* Bl = sB + lcur*NS;
        const float* Cl = sC + lcur*NS;
        float y = 0.f;
        #pragma unroll
        for (int n = 0; n < NS; n++){
            h[n] = h[n]*ex2f(dtc*A[n]) + dx*Bl[n];
            y += h[n]*Cl[n];
        }
        ysp[lcur*DD] = y + Dd*xvc;
        lcur = lnext; dtc = dtn; xvc = xvn;
    }
}

// ---------------- block reduction (sum, sumsq) over 512 threads ------------
__device__ __forceinline__ float2 blockReduce2(float a, float b){
    __shared__ float sa[16], sb[16];
    __shared__ float2 res;
    int lane = threadIdx.x & 31, w = threadIdx.x >> 5;
    #pragma unroll
    for (int o = 16; o; o >>= 1){
        a += __shfl_xor_sync(0xffffffffu, a, o);
        b += __shfl_xor_sync(0xffffffffu, b, o);
    }
    __syncthreads();
    if (lane == 0){ sa[w] = a; sb[w] = b; }
    __syncthreads();
    if (w == 0){
        a = (lane < 16) ? sa[lane] : 0.f;
        b = (lane < 16) ? sb[lane] : 0.f;
        #pragma unroll
        for (int o = 8; o; o >>= 1){
            a += __shfl_xor_sync(0xffffffffu, a, o);
            b += __shfl_xor_sync(0xffffffffu, b, o);
        }
        if (lane == 0){ res.x = a; res.y = b; }
    }
    __syncthreads();
    return res;
}

// ---------------- K7: combine dirs + LN + silu(z) gate, CHUNKED over l -----
// grid (64 slots, 4 chunks) x 512 threads. v-space: ys sums uniformly over k.
#define CHL 13
__global__ void __launch_bounds__(512)
k_combine(const float* __restrict__ og_, const float* __restrict__ ob_){
    __shared__ float sv[CHL*DD];
    __shared__ float smu[16], srs[16];
    int s = blockIdx.x, chunk = blockIdx.y, d = threadIdx.x;
    int e = g_topi[s];
    int l0 = chunk*CHL;
    int nl = (chunk < 3) ? CHL : (LL - 3*CHL);   // 13,13,13,10
    const float* y0 = g_ys + (size_t)(s*KDn + 0)*LL*DD;
    const float* y1 = g_ys + (size_t)(s*KDn + 1)*LL*DD;
    const float* y2 = g_ys + (size_t)(s*KDn + 2)*LL*DD;
    const float* y3 = g_ys + (size_t)(s*KDn + 3)*LL*DD;
    for (int t = 0; t < nl; t++){
        int o = (l0 + t)*DD + d;
        sv[t*DD + d] = y0[o] + y1[o] + y2[o] + y3[o];
    }
    __syncthreads();
    int w = d >> 5, lane = d & 31;
    if (w < nl){
        int t = w;
        float a = 0.f, s2 = 0.f;
        #pragma unroll
        for (int jj = 0; jj < 16; jj++){
            float xv = sv[t*DD + lane + 32*jj];
            a += xv; s2 += xv*xv;
        }
        #pragma unroll
        for (int o = 16; o; o >>= 1){
            a  += __shfl_xor_sync(0xffffffffu, a, o);
            s2 += __shfl_xor_sync(0xffffffffu, s2, o);
        }
        if (lane == 0){
            float mu = a*(1.f/512.f);
            float var = s2*(1.f/512.f) - mu*mu;
            smu[t] = mu;
            srs[t] = rsqrtf(var + 1e-5f);
        }
    }
    __syncthreads();
    float og = og_[e*DD+d], ob = ob_[e*DD+d];
    const float* zrow = g_z + (size_t)s*LL*DD + d;
    float pooled = 0.f;
    for (int t = 0; t < nl; t++){
        int l = l0 + t;
        float v = sv[t*DD + d];
        float yn = (v - smu[t])*srs[t]*og + ob;
        float z = zrow[l*DD];
        pooled += yn * (z / (1.f + __expf(-z)));
    }
    g_poolp[(chunk*NSLOT + s)*DD + d] = pooled;
}

// ---------------- K8: final pooled LN per slot + top-2 mix + aux -----------
__global__ void __launch_bounds__(512)
k_mix(float* __restrict__ out, int out_size,
      const float* __restrict__ ng_, const float* __restrict__ nb_){
    int b = blockIdx.x, d = threadIdx.x;
    float res = 0.f;
    #pragma unroll 1
    for (int j = 0; j < 2; j++){
        int s = b*2 + j;
        int e = g_topi[s];
        float pooled = (g_poolp[(0*NSLOT + s)*DD + d]
                      + g_poolp[(1*NSLOT + s)*DD + d]
                      + g_poolp[(2*NSLOT + s)*DD + d]
                      + g_poolp[(3*NSLOT + s)*DD + d]) * (1.f/49.f);
        float2 ss = blockReduce2(pooled, pooled*pooled);
        float mu = ss.x*(1.f/512.f);
        float var = ss.y*(1.f/512.f) - mu*mu;
        float rs = rsqrtf(var + 1e-5f);
        float yn = (pooled - mu)*rs*ng_[e*DD+d] + nb_[e*DD+d];
        res += g_topv[s] * yn;
    }
    out[b*DD + d] = res;
    if (b == 0 && d == 0 && out_size > BB*DD) out[BB*DD] = g_aux;
}

// ---------------- launch ----------------------------------------------------
extern "C" void kernel_launch(void* const* d_in, const int* in_sizes, int n_in,
                              void* d_out, int out_size){
    const float* x    = (const float*)d_in[0];
    const float* wg   = (const float*)d_in[1];
    const float* bg   = (const float*)d_in[2];
    const float* ipw  = (const float*)d_in[3];
    const float* ipb  = (const float*)d_in[4];
    const float* cw   = (const float*)d_in[5];
    const float* cb   = (const float*)d_in[6];
    const float* xpw  = (const float*)d_in[7];
    const float* dtw  = (const float*)d_in[8];
    const float* dtb  = (const float*)d_in[9];
    const float* alog = (const float*)d_in[10];
    const float* ds   = (const float*)d_in[11];
    const float* ong  = (const float*)d_in[12];
    const float* onb  = (const float*)d_in[13];
    const float* ng   = (const float*)d_in[14];
    const float* nb   = (const float*)d_in[15];
    float* out = (float*)d_out;

    cudaFuncSetAttribute(k_inproj, cudaFuncAttributeMaxDynamicSharedMemorySize, IP_SMEM);
    cudaFuncSetAttribute(k_xdbl,   cudaFuncAttributeMaxDynamicSharedMemorySize, XD_SMEM);

    k_wt      <<<dim3(EE, 8, 16), dim3(32, 8)>>>(xpw);
    k_wt2     <<<dim3(EE*KDn, 16), dim3(32, 8)>>>(dtw);
    k_gate    <<<BB, 512>>>(x, wg, bg);
    k_inproj  <<<dim3(NSLOT, 2), 512, IP_SMEM>>>(x, ipw, ipb, cw, cb);
    k_xdbl    <<<dim3(NSLOT, 2), 512, XD_SMEM>>>(dtb);
    k_scan    <<<NSLOT*KDn, 512>>>(alog, ds);
    k_combine <<<dim3(NSLOT, 4), 512>>>(ong, onb);
    k_mix     <<<BB, 512>>>(out, out_size, ng, nb);
}

// round 17
// speedup vs baseline: 1.0726x; 1.0244x over previous
#include <cuda_runtime.h>
#include <math.h>

// Problem constants
#define EE  4      // experts
#define BB  32     // batch
#define HH  7
#define LL  49     // H*W
#define DD  512    // dim
#define C2  1024   // 2*dim
#define RR  32     // DT_RANK
#define NS  16     // N_STATE
#define KDn 4      // directions
#define NSLOT (BB*2)   // 64 selected (b, expert) slots

// ---------------- scratch (device globals; no allocation allowed) ----------
__device__ float g_v [NSLOT*LL*DD];          // conv output v, slot-indexed (v-space)
__device__ float g_z [NSLOT*LL*DD];          // z half, slot-indexed
__device__ float g_ys[NSLOT*KDn*LL*DD];      // scan outputs (v-space)
__device__ float g_dt[NSLOT*KDn*LL*DD];      // softplus(dt) (v-space)
__device__ float g_Bm[NSLOT*KDn*LL*NS];      // B (v-space)
__device__ float g_Cm[NSLOT*KDn*LL*NS];      // C (v-space)
__device__ float g_xpwT[EE*DD*256];          // transposed x_proj_w: [e][d][k*64+c]
__device__ float g_dtwT[EE*KDn*RR*DD];       // transposed dt_proj_w: [e][k][r][d]
__device__ float g_poolp[4*NSLOT*DD];        // partial pooled sums per l-chunk
__device__ float g_raw[BB*EE];
__device__ float g_aux;
__device__ int   g_ctr;                      // last-block-done counter (self-reset)
__device__ int   g_topi[NSLOT];              // slot s -> expert  (b = s>>1)
__device__ float g_topv[NSLOT];              // slot s -> gate coeff

// ---------------- f32x2 packed FMA helpers (sm_103a) -----------------------
__device__ __forceinline__ unsigned long long pk2(float lo, float hi){
    unsigned long long r;
    asm("mov.b64 %0, {%1, %2};" : "=l"(r) : "f"(lo), "f"(hi));
    return r;
}
__device__ __forceinline__ void fma2(unsigned long long& d, unsigned long long a, unsigned long long b){
    asm("fma.rn.f32x2 %0, %1, %2, %0;" : "+l"(d) : "l"(a), "l"(b));
}
__device__ __forceinline__ void upk2(unsigned long long v, float& lo, float& hi){
    asm("mov.b64 {%0, %1}, %2;" : "=f"(lo), "=f"(hi) : "l"(v));
}
__device__ __forceinline__ float ex2f(float x){
    float r; asm("ex2.approx.f32 %0, %1;" : "=f"(r) : "f"(x)); return r;
}
__device__ __forceinline__ float lg2f(float x){
    float r; asm("lg2.approx.f32 %0, %1;" : "=f"(r) : "f"(x)); return r;
}
__device__ __forceinline__ void cp_async16(float* smem_dst, const float* gmem_src){
    unsigned saddr;
    asm("{ .reg .u64 t; cvta.to.shared.u64 t, %1; cvt.u32.u64 %0, t; }"
        : "=r"(saddr) : "l"(smem_dst));
    asm volatile("cp.async.cg.shared.global [%0], [%1], 16;"
                 :: "r"(saddr), "l"(gmem_src));
}

// ---------------- K0a: coalesced tiled transpose xpw -> g_xpwT -------------
__global__ void k_wt(const float* __restrict__ xpw_){
    __shared__ float tile[32][33];
    int e = blockIdx.x, kt = blockIdx.y, dt = blockIdx.z;
    int tx = threadIdx.x, ty = threadIdx.y;
    #pragma unroll
    for (int i = 0; i < 4; i++){
        int kc = kt*32 + ty + 8*i;
        tile[ty + 8*i][tx] = xpw_[((size_t)e*256 + kc)*DD + dt*32 + tx];
    }
    __syncthreads();
    #pragma unroll
    for (int i = 0; i < 4; i++){
        int d = dt*32 + ty + 8*i;
        g_xpwT[(size_t)e*DD*256 + (size_t)d*256 + kt*32 + tx] = tile[tx][ty + 8*i];
    }
}

// ---------------- K0b: coalesced tiled transpose dtw -> g_dtwT -------------
__global__ void k_wt2(const float* __restrict__ dtw_){
    __shared__ float tile[32][33];
    int ek = blockIdx.x, dt = blockIdx.y;
    int tx = threadIdx.x, ty = threadIdx.y;
    const float* src = dtw_ + (size_t)ek*DD*RR;
    float* dst = g_dtwT + (size_t)ek*DD*RR;
    #pragma unroll
    for (int i = 0; i < 4; i++){
        int d = dt*32 + ty + 8*i;
        tile[ty + 8*i][tx] = src[(size_t)d*RR + tx];
    }
    __syncthreads();
    #pragma unroll
    for (int i = 0; i < 4; i++){
        int r = ty + 8*i;
        dst[(size_t)r*DD + dt*32 + tx] = tile[tx][r];
    }
}

// ---------------- K1: gate softmax + fused top-k/aux (last block) ----------
__global__ void k_gate(const float* __restrict__ x, const float* __restrict__ wg,
                       const float* __restrict__ bg){
    int b = blockIdx.x, tid = threadIdx.x;
    const float* xb = x + (size_t)b*LL*DD + tid;
    float s = 0.f;
    #pragma unroll 7
    for (int l = 0; l < LL; l++) s += xb[l*DD];
    s *= (1.f/49.f);
    float p0 = s*wg[tid*EE+0], p1 = s*wg[tid*EE+1];
    float p2 = s*wg[tid*EE+2], p3 = s*wg[tid*EE+3];
    #pragma unroll
    for (int o = 16; o; o >>= 1){
        p0 += __shfl_xor_sync(0xffffffffu, p0, o);
        p1 += __shfl_xor_sync(0xffffffffu, p1, o);
        p2 += __shfl_xor_sync(0xffffffffu, p2, o);
        p3 += __shfl_xor_sync(0xffffffffu, p3, o);
    }
    __shared__ float sp[16][4];
    int w = tid >> 5, lane = tid & 31;
    if (lane == 0){ sp[w][0]=p0; sp[w][1]=p1; sp[w][2]=p2; sp[w][3]=p3; }
    __syncthreads();
    if (tid == 0){
        float lg[4];
        for (int e = 0; e < 4; e++){
            float a = bg[e];
            for (int ww = 0; ww < 16; ww++) a += sp[ww][e];
            lg[e] = a;
        }
        float m = fmaxf(fmaxf(lg[0],lg[1]), fmaxf(lg[2],lg[3]));
        float ex[4], se = 0.f;
        for (int e = 0; e < 4; e++){ ex[e] = expf(lg[e]-m); se += ex[e]; }
        for (int e = 0; e < 4; e++) g_raw[b*4+e] = ex[e]/se;
    }
    __shared__ int sdone;
    if (tid == 0){
        __threadfence();
        int old = atomicAdd(&g_ctr, 1);
        sdone = (old == BB-1) ? 1 : 0;
    }
    __syncthreads();
    if (sdone){
        __threadfence();
        __shared__ float sraw[32][4];
        __shared__ float smask[32][4];
        __shared__ float sden[4];
        if (tid < 32){
            int bb = tid;
            float r[4];
            #pragma unroll
            for (int e = 0; e < 4; e++){ r[e] = g_raw[bb*4+e]; sraw[bb][e] = r[e]; }
            int i0 = 0; float m0 = r[0];
            #pragma unroll
            for (int e = 1; e < 4; e++) if (r[e] > m0){ m0 = r[e]; i0 = e; }
            int i1 = -1; float m1 = -1e30f;
            #pragma unroll
            for (int e = 0; e < 4; e++) if (e != i0 && r[e] > m1){ m1 = r[e]; i1 = e; }
            #pragma unroll
            for (int e = 0; e < 4; e++) smask[bb][e] = (e==i0 || e==i1) ? 1.f : 0.f;
        }
        __syncthreads();
        if (tid == 0){
            float aux = 0.f;
            for (int e = 0; e < 4; e++){
                float ds = 0.f, imp = 0.f, ld = 0.f;
                for (int bb = 0; bb < 32; bb++){
                    ds  += sraw[bb][e]*smask[bb][e];
                    imp += sraw[bb][e];
                    ld  += smask[bb][e];
                }
                sden[e] = ds + 1e-6f;
                imp *= (1.f/32.f); ld *= (1.f/32.f);
                aux += (ld-imp)*(ld-imp);
            }
            g_aux = 0.01f * aux * 0.25f;
        }
        __syncthreads();
        if (tid < 32){
            int bb = tid;
            float r[4];
            #pragma unroll
            for (int e = 0; e < 4; e++) r[e] = sraw[bb][e];
            int i0 = 0; float m0 = r[0];
            #pragma unroll
            for (int e = 1; e < 4; e++) if (r[e] > m0){ m0 = r[e]; i0 = e; }
            int i1 = -1; float m1 = -1e30f;
            #pragma unroll
            for (int e = 0; e < 4; e++) if (e != i0 && r[e] > m1){ m1 = r[e]; i1 = e; }
            const float cap = 40.f;   // int(1.25*32)
            float s0 = r[i0]*cap/sden[i0];
            float s1 = r[i1]*cap/sden[i1];
            int a0 = i0, a1 = i1; float v0 = s0, v1 = s1;
            if (v1 > v0 || (v1 == v0 && a1 < a0)){
                int t = a0; a0 = a1; a1 = t;
                float tv = v0; v0 = v1; v1 = tv;
            }
            g_topi[bb*2] = a0; g_topi[bb*2+1] = a1;
            g_topv[bb*2] = v0; g_topv[bb*2+1] = v1;
        }
        __syncthreads();
        if (tid == 0) g_ctr = 0;
    }
}

// ---------------- K3: in_proj GEMM + fused depthwise conv -> g_v -----------
// grid (64 slots, 2 roles) x 512 threads. sx TRANSPOSED in smem (stride 52).
// Weights stream global->smem via cp.async double buffer (8-kk stages); the
// consumer reads conflict-free LDS, removing all exposed LDG latency.
// sxin (role 0 conv staging) ALIASES the dead sxT region after the GEMM.
#define SXS 52
#define WST 4096                        // floats per stage (8 kk x 512 cols)
#define IP_SMEM ((DD*SXS + 2*WST)*4)    // 106496 + 32768 = 139264
__global__ void __launch_bounds__(512, 1)
k_inproj(const float* __restrict__ x, const float* __restrict__ Wi,
         const float* __restrict__ bi, const float* __restrict__ cw,
         const float* __restrict__ cb){
    extern __shared__ float sm_[];
    float* sxT  = sm_;                  // [DD][SXS]
    float* sxin = sm_;                  // alias: reused for conv input (role 0)
    float* wbuf = sm_ + DD*SXS;         // 2 x WST
    int s = blockIdx.x, role = blockIdx.y, tid = threadIdx.x;
    int b = s >> 1;
    int e = g_topi[s];
    const float* xb = x + (size_t)b*LL*DD;
    for (int i = tid; i < LL*DD; i += 512){
        int l = i >> 9, d = i & 511;
        sxT[d*SXS + l] = xb[i];
    }
    {
        int d = tid;
        sxT[d*SXS + 49] = 0.f; sxT[d*SXS + 50] = 0.f; sxT[d*SXS + 51] = 0.f;
    }

    int cth = tid & 255, lg = tid >> 8;
    int c0 = cth*2;
    int lbase = lg*24;                  // 0 or 24; 16B-aligned in sxT rows
    const float* Wbase = Wi + (size_t)e*DD*C2 + role*DD;
    float2 bia = *(const float2*)(bi + e*C2 + role*DD + c0);
    float* zout = g_z + (size_t)s*LL*DD;

    // preload weight stages 0 and 1
    #pragma unroll
    for (int st0 = 0; st0 < 2; st0++){
        const float* src = Wbase + (size_t)st0*8*C2;
        float* dst = wbuf + st0*WST;
        #pragma unroll
        for (int u = 0; u < 2; u++){
            int ch = tid + u*512;
            int r = ch >> 7, col = (ch & 127) << 2;
            cp_async16(dst + r*512 + col, src + (size_t)r*C2 + col);
        }
        asm volatile("cp.async.commit_group;");
    }
    __syncthreads();   // sxT transpose complete

    unsigned long long acc0[14], acc1[14];
    #pragma unroll
    for (int p = 0; p < 14; p++){ acc0[p] = 0ull; acc1[p] = 0ull; }

    #pragma unroll 1
    for (int st = 0; st < 64; st++){
        asm volatile("cp.async.wait_group 1;");
        __syncthreads();
        const float* wst = wbuf + (st & 1)*WST;
        #pragma unroll
        for (int kl = 0; kl < 8; kl++){
            float2 w = *(const float2*)(wst + kl*512 + c0);
            unsigned long long w0 = pk2(w.x, w.x);
            unsigned long long w1 = pk2(w.y, w.y);
            const ulonglong2* xr = (const ulonglong2*)(sxT + (st*8 + kl)*SXS + lbase);
            #pragma unroll
            for (int q = 0; q < 7; q++){
                ulonglong2 xq = xr[q];          // LDS.128: pairs (2q, 2q+1)
                fma2(acc0[2*q],   w0, xq.x);
                fma2(acc1[2*q],   w1, xq.x);
                fma2(acc0[2*q+1], w0, xq.y);
                fma2(acc1[2*q+1], w1, xq.y);
            }
        }
        __syncthreads();   // all reads of buffer (st&1) done block-wide
        if (st + 2 < 64){
            const float* src = Wbase + (size_t)(st+2)*8*C2;
            float* dst = wbuf + (st & 1)*WST;
            #pragma unroll
            for (int u = 0; u < 2; u++){
                int ch = tid + u*512;
                int r = ch >> 7, col = (ch & 127) << 2;
                cp_async16(dst + r*512 + col, src + (size_t)r*C2 + col);
            }
            asm volatile("cp.async.commit_group;");
        }
    }
    // After final stage sync: all sxT reads complete; sxin alias is safe.

    #pragma unroll
    for (int p = 0; p < 14; p++){
        int l0 = lbase + 2*p, l1 = l0 + 1;
        float a00, a01, a10, a11;
        upk2(acc0[p], a00, a01);
        upk2(acc1[p], a10, a11);
        if (l0 < LL){
            float2 o = make_float2(a00 + bia.x, a10 + bia.y);
            if (role == 0) *(float2*)(sxin + (size_t)l0*DD + c0) = o;
            else           *(float2*)(zout + (size_t)l0*DD + c0) = o;
        }
        if (l1 < LL){
            float2 o = make_float2(a01 + bia.x, a11 + bia.y);
            if (role == 0) *(float2*)(sxin + (size_t)l1*DD + c0) = o;
            else           *(float2*)(zout + (size_t)l1*DD + c0) = o;
        }
    }
    if (role != 0) return;
    __syncthreads();
    // ---- depthwise 3x3 conv + silu -> g_v (single write); d = tid ----
    float* vout = g_v + (size_t)s*LL*DD;
    {
        int d = tid;
        float w9[9];
        #pragma unroll
        for (int t = 0; t < 9; t++) w9[t] = cw[(e*DD+d)*9 + t];
        float bias = cb[e*DD+d];
        float row[3][7];
        #pragma unroll
        for (int j = 0; j < 7; j++){
            row[0][j] = sxin[(0*7+j)*DD + d];
            row[1][j] = sxin[(1*7+j)*DD + d];
        }
        #pragma unroll
        for (int i = 0; i < 7; i++){
            if (i < 6){
                #pragma unroll
                for (int j = 0; j < 7; j++)
                    row[(i+1)%3][j] = sxin[((i+1)*7+j)*DD + d];
            }
            const float* rm = (i > 0) ? row[(i-1)%3] : nullptr;
            const float* rc = row[i%3];
            const float* rp = (i < 6) ? row[(i+1)%3] : nullptr;
            #pragma unroll
            for (int j = 0; j < 7; j++){
                float a = bias;
                #pragma unroll
                for (int dj = 0; dj < 3; dj++){
                    int jj = j + dj - 1;
                    if (jj < 0 || jj > 6) continue;
                    if (i > 0) a += rm[jj]*w9[0*3+dj];
                    a += rc[jj]*w9[1*3+dj];
                    if (i < 6) a += rp[jj]*w9[2*3+dj];
                }
                float v = a / (1.f + __expf(-a));   // silu
                vout[(i*7+j)*DD + d] = v;
            }
        }
    }
}

// ---------------- K5a: merged x_dbl GEMM (all 4 dirs) + dt_proj ------------
#define SX2 52
#define XD_SMEM ((DD*SX2 + 128*SX2)*4)   // 106496 + 26624 = 133120
__global__ void __launch_bounds__(512, 1)
k_xdbl(const float* __restrict__ dtb_){
    extern __shared__ float sm[];
    float* vT = sm;                  // [DD][SX2]
    float* sY = sm + DD*SX2;         // [128][SX2]
    int s = blockIdx.x, role = blockIdx.y, tid = threadIdx.x;
    int e = g_topi[s];

    const float* vsrc = g_v + (size_t)s*LL*DD;
    for (int i = tid; i < LL*DD; i += 512){
        int l = i >> 9, d = i & 511;
        vT[d*SX2 + l] = vsrc[i];
    }
    { int d = tid; vT[d*SX2+49]=0.f; vT[d*SX2+50]=0.f; vT[d*SX2+51]=0.f; }
    __syncthreads();

    int cth = tid & 63, lg = tid >> 6;
    int kc0 = role*128 + cth*2;
    int lbase = (lg < 6) ? lg*6 : 36 + (lg-6)*8;
    int np    = (lg < 6) ? 3 : 4;
    unsigned long long a0[4], a1[4];
    #pragma unroll
    for (int p = 0; p < 4; p++){ a0[p] = 0ull; a1[p] = 0ull; }
    const float* Wp = g_xpwT + (size_t)e*DD*256 + kc0;
    #pragma unroll 8
    for (int kk = 0; kk < DD; kk++){
        float2 w = *(const float2*)(Wp + (size_t)kk*256);
        unsigned long long w0 = pk2(w.x, w.x);
        unsigned long long w1 = pk2(w.y, w.y);
        const float* xr = vT + kk*SX2 + lbase;
        #pragma unroll
        for (int p = 0; p < 4; p++){
            if (p < np){
                unsigned long long xp = *(const unsigned long long*)(xr + 2*p);
                fma2(a0[p], w0, xp);
                fma2(a1[p], w1, xp);
            }
        }
    }
    {
        int cl0 = cth*2;
        #pragma unroll
        for (int p = 0; p < 4; p++){
            if (p < np){
                float lo, hi;
                upk2(a0[p], lo, hi);
                sY[cl0*SX2 + lbase + 2*p] = lo;  sY[cl0*SX2 + lbase + 2*p + 1] = hi;
                upk2(a1[p], lo, hi);
                sY[(cl0+1)*SX2 + lbase + 2*p] = lo;  sY[(cl0+1)*SX2 + lbase + 2*p + 1] = hi;
            }
        }
    }
    __syncthreads();

    for (int i = tid; i < 2*LL*NS; i += 512){
        int kloc = i / (LL*NS);
        int rem  = i - kloc*LL*NS;
        int l = rem >> 4, n = rem & 15;
        int k = role*2 + kloc;
        g_Bm[((size_t)(s*KDn + k)*LL + l)*NS + n] = sY[(kloc*64 + 32 + n)*SX2 + l];
        g_Cm[((size_t)(s*KDn + k)*LL + l)*NS + n] = sY[(kloc*64 + 48 + n)*SX2 + l];
    }

    int dd = tid;
    const float L2E = 1.44269504088896f;
    const float LN2 = 0.69314718055995f;
    #pragma unroll 1
    for (int kloc = 0; kloc < 2; kloc++){
        int k = role*2 + kloc;
        float bias = dtb_[(e*KDn + k)*DD + dd];
        float wreg[32];
        {
            const float* wt = g_dtwT + (size_t)(e*KDn + k)*DD*RR + dd;
            #pragma unroll
            for (int r = 0; r < RR; r++) wreg[r] = wt[(size_t)r*DD];
        }
        unsigned long long acc[26];
        unsigned long long binit = pk2(bias, bias);
        #pragma unroll
        for (int t = 0; t < 26; t++) acc[t] = binit;
        const float* sb = sY + (kloc*64)*SX2;
        #pragma unroll 4
        for (int r = 0; r < RR; r++){
            unsigned long long wd = pk2(wreg[r], wreg[r]);
            const float* srow = sb + r*SX2;
            #pragma unroll
            for (int t = 0; t < 26; t++){
                unsigned long long xp = *(const unsigned long long*)(srow + 2*t);
                fma2(acc[t], wd, xp);
            }
        }
        float* dtout = g_dt + (size_t)(s*KDn + k)*LL*DD + dd;
        #pragma unroll
        for (int t = 0; t < 26; t++){
            float a_lo, a_hi;
            upk2(acc[t], a_lo, a_hi);
            int l0 = 2*t, l1 = 2*t + 1;
            if (l0 < LL){
                float dtv = fmaxf(a_lo, 0.f) + LN2*lg2f(1.f + ex2f(-fabsf(a_lo)*L2E));
                dtout[l0*DD] = dtv;
            }
            if (l1 < LL){
                float dtv = fmaxf(a_hi, 0.f) + LN2*lg2f(1.f + ex2f(-fabsf(a_hi)*L2E));
                dtout[l1*DD] = dtv;
            }
        }
    }
}

// ---------------- K5b: selective scan (v-space, ALU permutation) -----------
__device__ __forceinline__ int permf(int k, int t){
    int tt = (k & 1) ? (48 - t) : t;
    if (k >= 2){
        int q = tt / 7;
        return (tt - 7*q)*7 + q;
    }
    return tt;
}
__global__ void __launch_bounds__(512, 2)
k_scan(const float* __restrict__ alog_, const float* __restrict__ ds_){
    __shared__ float sB[LL*NS];
    __shared__ float sC[LL*NS];
    int idx = blockIdx.x;
    int k = idx & 3, s = idx >> 2;
    int e = g_topi[s];
    int dd = threadIdx.x;
    size_t skbase = (size_t)(s*KDn + k);
    {
        const float* Bg = g_Bm + skbase*LL*NS;
        const float* Cg = g_Cm + skbase*LL*NS;
        for (int i = dd; i < LL*NS; i += 512){ sB[i] = Bg[i]; sC[i] = Cg[i]; }
    }
    float A[NS];
    {
        const float4* al = (const float4*)(alog_ + ((size_t)((e*KDn+k)*DD) + dd)*NS);
        const float L2E = 1.44269504088896f;
        #pragma unroll
        for (int q = 0; q < 4; q++){
            float4 v = al[q];
            A[q*4+0] = -__expf(v.x)*L2E; A[q*4+1] = -__expf(v.y)*L2E;
            A[q*4+2] = -__expf(v.z)*L2E; A[q*4+3] = -__expf(v.w)*L2E;
        }
    }
    float Dd = ds_[(e*KDn+k)*DD + dd];
    const float* dtp = g_dt + skbase*LL*DD + dd;
    const float* vp  = g_v  + (size_t)s*LL*DD + dd;
    float*       ysp = g_ys + skbase*LL*DD + dd;
    __syncthreads();
    float h[NS];
    #pragma unroll
    for (int n = 0; n < NS; n++) h[n] = 0.f;
    int lcur = permf(k, 0);
    float dtc = dtp[lcur*DD], xvc = vp[lcur*DD];
    #pragma unroll 1
    for (int t = 0; t < LL; t++){
        int lnext = (t < LL-1) ? permf(k, t+1) : 0;
        float dtn = 0.f, xvn = 0.f;
        if (t < LL-1){ dtn = dtp[lnext*DD]; xvn = vp[lnext*DD]; }
        float dx = dtc*xvc;
        const float* Bl = sB + lcur*NS;
        const float* Cl = sC + lcur*NS;
        float y = 0.f;
        #pragma unroll
        for (int n = 0; n < NS; n++){
            h[n] = h[n]*ex2f(dtc*A[n]) + dx*Bl[n];
            y += h[n]*Cl[n];
        }
        ysp[lcur*DD] = y + Dd*xvc;
        lcur = lnext; dtc = dtn; xvc = xvn;
    }
}

// ---------------- block reduction (sum, sumsq) over 512 threads ------------
__device__ __forceinline__ float2 blockReduce2(float a, float b){
    __shared__ float sa[16], sb[16];
    __shared__ float2 res;
    int lane = threadIdx.x & 31, w = threadIdx.x >> 5;
    #pragma unroll
    for (int o = 16; o; o >>= 1){
        a += __shfl_xor_sync(0xffffffffu, a, o);
        b += __shfl_xor_sync(0xffffffffu, b, o);
    }
    __syncthreads();
    if (lane == 0){ sa[w] = a; sb[w] = b; }
    __syncthreads();
    if (w == 0){
        a = (lane < 16) ? sa[lane] : 0.f;
        b = (lane < 16) ? sb[lane] : 0.f;
        #pragma unroll
        for (int o = 8; o; o >>= 1){
            a += __shfl_xor_sync(0xffffffffu, a, o);
            b += __shfl_xor_sync(0xffffffffu, b, o);
        }
        if (lane == 0){ res.x = a; res.y = b; }
    }
    __syncthreads();
    return res;
}

// ---------------- K7: combine dirs + LN + silu(z) gate, CHUNKED over l -----
#define CHL 13
__global__ void __launch_bounds__(512)
k_combine(const float* __restrict__ og_, const float* __restrict__ ob_){
    __shared__ float sv[CHL*DD];
    __shared__ float smu[16], srs[16];
    int s = blockIdx.x, chunk = blockIdx.y, d = threadIdx.x;
    int e = g_topi[s];
    int l0 = chunk*CHL;
    int nl = (chunk < 3) ? CHL : (LL - 3*CHL);   // 13,13,13,10
    const float* y0 = g_ys + (size_t)(s*KDn + 0)*LL*DD;
    const float* y1 = g_ys + (size_t)(s*KDn + 1)*LL*DD;
    const float* y2 = g_ys + (size_t)(s*KDn + 2)*LL*DD;
    const float* y3 = g_ys + (size_t)(s*KDn + 3)*LL*DD;
    for (int t = 0; t < nl; t++){
        int o = (l0 + t)*DD + d;
        sv[t*DD + d] = y0[o] + y1[o] + y2[o] + y3[o];
    }
    __syncthreads();
    int w = d >> 5, lane = d & 31;
    if (w < nl){
        int t = w;
        float a = 0.f, s2 = 0.f;
        #pragma unroll
        for (int jj = 0; jj < 16; jj++){
            float xv = sv[t*DD + lane + 32*jj];
            a += xv; s2 += xv*xv;
        }
        #pragma unroll
        for (int o = 16; o; o >>= 1){
            a  += __shfl_xor_sync(0xffffffffu, a, o);
            s2 += __shfl_xor_sync(0xffffffffu, s2, o);
        }
        if (lane == 0){
            float mu = a*(1.f/512.f);
            float var = s2*(1.f/512.f) - mu*mu;
            smu[t] = mu;
            srs[t] = rsqrtf(var + 1e-5f);
        }
    }
    __syncthreads();
    float og = og_[e*DD+d], ob = ob_[e*DD+d];
    const float* zrow = g_z + (size_t)s*LL*DD + d;
    float pooled = 0.f;
    for (int t = 0; t < nl; t++){
        int l = l0 + t;
        float v = sv[t*DD + d];
        float yn = (v - smu[t])*srs[t]*og + ob;
        float z = zrow[l*DD];
        pooled += yn * (z / (1.f + __expf(-z)));
    }
    g_poolp[(chunk*NSLOT + s)*DD + d] = pooled;
}

// ---------------- K8: final pooled LN per slot + top-2 mix + aux -----------
__global__ void __launch_bounds__(512)
k_mix(float* __restrict__ out, int out_size,
      const float* __restrict__ ng_, const float* __restrict__ nb_){
    int b = blockIdx.x, d = threadIdx.x;
    float res = 0.f;
    #pragma unroll 1
    for (int j = 0; j < 2; j++){
        int s = b*2 + j;
        int e = g_topi[s];
        float pooled = (g_poolp[(0*NSLOT + s)*DD + d]
                      + g_poolp[(1*NSLOT + s)*DD + d]
                      + g_poolp[(2*NSLOT + s)*DD + d]
                      + g_poolp[(3*NSLOT + s)*DD + d]) * (1.f/49.f);
        float2 ss = blockReduce2(pooled, pooled*pooled);
        float mu = ss.x*(1.f/512.f);
        float var = ss.y*(1.f/512.f) - mu*mu;
        float rs = rsqrtf(var + 1e-5f);
        float yn = (pooled - mu)*rs*ng_[e*DD+d] + nb_[e*DD+d];
        res += g_topv[s] * yn;
    }
    out[b*DD + d] = res;
    if (b == 0 && d == 0 && out_size > BB*DD) out[BB*DD] = g_aux;
}

// ---------------- launch ----------------------------------------------------
extern "C" void kernel_launch(void* const* d_in, const int* in_sizes, int n_in,
                              void* d_out, int out_size){
    const float* x    = (const float*)d_in[0];
    const float* wg   = (const float*)d_in[1];
    const float* bg   = (const float*)d_in[2];
    const float* ipw  = (const float*)d_in[3];
    const float* ipb  = (const float*)d_in[4];
    const float* cw   = (const float*)d_in[5];
    const float* cb   = (const float*)d_in[6];
    const float* xpw  = (const float*)d_in[7];
    const float* dtw  = (const float*)d_in[8];
    const float* dtb  = (const float*)d_in[9];
    const float* alog = (const float*)d_in[10];
    const float* ds   = (const float*)d_in[11];
    const float* ong  = (const float*)d_in[12];
    const float* onb  = (const float*)d_in[13];
    const float* ng   = (const float*)d_in[14];
    const float* nb   = (const float*)d_in[15];
    float* out = (float*)d_out;

    cudaFuncSetAttribute(k_inproj, cudaFuncAttributeMaxDynamicSharedMemorySize, IP_SMEM);
    cudaFuncSetAttribute(k_xdbl,   cudaFuncAttributeMaxDynamicSharedMemorySize, XD_SMEM);

    k_wt      <<<dim3(EE, 8, 16), dim3(32, 8)>>>(xpw);
    k_wt2     <<<dim3(EE*KDn, 16), dim3(32, 8)>>>(dtw);
    k_gate    <<<BB, 512>>>(x, wg, bg);
    k_inproj  <<<dim3(NSLOT, 2), 512, IP_SMEM>>>(x, ipw, ipb, cw, cb);
    k_xdbl    <<<dim3(NSLOT, 2), 512, XD_SMEM>>>(dtb);
    k_scan    <<<NSLOT*KDn, 512>>>(alog, ds);
    k_combine <<<dim3(NSLOT, 4), 512>>>(ong, onb);
    k_mix     <<<BB, 512>>>(out, out_size, ng, nb);
}